// round 7
// baseline (speedup 1.0000x reference)
#include <cuda_runtime.h>
#include <cstdint>

// out[b,c,i,j] = x[b,c, i^3, j^3]   (H = W = 256)
//
// Flattened over float4s: idx = (bc*256 + i)*64 + g, so i^3 is just
// idx ^ (3*64) = idx ^ 192, and j^3 within an aligned float4 is a lane
// reverse. The whole op is:  out[idx] = rev4(in[idx ^ 192]).
//
// 8 front-batched LDG.128 per thread (MLP=8), streaming cache hints,
// consecutive-blockIdx waves (keeps concurrent TLB footprint small).

static constexpr int UNROLL = 8;
static constexpr int TPB    = 256;

__global__ void __launch_bounds__(TPB)
dualswitch_kernel(const float4* __restrict__ in, float4* __restrict__ out) {
    int base = blockIdx.x * (TPB * UNROLL) + threadIdx.x;

    float4 v[UNROLL];
    #pragma unroll
    for (int u = 0; u < UNROLL; u++)
        v[u] = __ldcs(in + ((base + u * TPB) ^ 192));

    #pragma unroll
    for (int u = 0; u < UNROLL; u++)
        __stcs(out + (base + u * TPB), make_float4(v[u].w, v[u].z, v[u].y, v[u].x));
}

extern "C" void kernel_launch(void* const* d_in, const int* in_sizes, int n_in,
                              void* d_out, int out_size) {
    const float4* in  = (const float4*)d_in[0];
    float4*       out = (float4*)d_out;
    int total4 = out_size / 4;                 // 25,165,824
    int blocks = total4 / (TPB * UNROLL);      // exact: 12,288
    dualswitch_kernel<<<blocks, TPB>>>(in, out);
}

// round 9
// speedup vs baseline: 1.0171x; 1.0171x over previous
#include <cuda_runtime.h>
#include <cstdint>

// out[b,c,i,j] = x[b,c, i^3, j^3]   (H = W = 256)
// j^3 within an aligned float4 = lane reverse; i^3 = row shuffle.
// 8 float4s per thread, front-batched independent LDG.128 (MLP=8/thread),
// streaming cache hints (evict-first; zero reuse).
//
// NOTE: keep the decomposed index math (g/rest/i/bc). The algebraically
// equivalent `idx ^ 192` form regresses ~2.5% — ptxas schedules the load
// run worse (measured R6: DRAM 85.3%->80.3%).

static constexpr int W4 = 64;    // float4s per row
static constexpr int H  = 256;
static constexpr int UNROLL = 8;

__global__ void __launch_bounds__(256)
dualswitch_kernel(const float4* __restrict__ in, float4* __restrict__ out) {
    // Each block owns a contiguous chunk of 256*UNROLL float4s.
    int base = blockIdx.x * (256 * UNROLL) + threadIdx.x;

    float4 v[UNROLL];
    #pragma unroll
    for (int u = 0; u < UNROLL; u++) {
        int idx  = base + u * 256;
        int g    = idx & (W4 - 1);
        int rest = idx >> 6;
        int i    = rest & (H - 1);
        int bc   = rest >> 8;
        int in_idx = ((bc << 8) | (i ^ 3)) * W4 + g;
        v[u] = __ldcs(in + in_idx);
    }

    #pragma unroll
    for (int u = 0; u < UNROLL; u++) {
        int idx = base + u * 256;
        __stcs(out + idx, make_float4(v[u].w, v[u].z, v[u].y, v[u].x));
    }
}

extern "C" void kernel_launch(void* const* d_in, const int* in_sizes, int n_in,
                              void* d_out, int out_size) {
    const float4* in  = (const float4*)d_in[0];
    float4*       out = (float4*)d_out;
    int total4 = out_size / 4;                     // 25,165,824
    int blocks = total4 / (256 * UNROLL);          // exact: 12,288
    dualswitch_kernel<<<blocks, 256>>>(in, out);
}

// round 10
// speedup vs baseline: 1.0193x; 1.0021x over previous
#include <cuda_runtime.h>
#include <cstdint>

// out[b,c,i,j] = x[b,c, i^3, j^3]   (H = W = 256)
//
// The permutation is an involution, so instead of gathering
// (out[idx] = rev4(in[idx^192])) we scatter:
//     out[idx ^ 192] = rev4(in[idx])
// This makes the 8-load run purely linear off one base register
// (LDG.E.128 [R, imm] x8, zero ALU in the load batch -> max MLP_eff);
// the XOR lands on the stores, which are issue-only and don't block.
// Coalescing identical both ways (warp spans 512B contiguous; ^192 is
// uniform within each 64-thread group).

static constexpr int UNROLL = 8;
static constexpr int TPB    = 256;

__global__ void __launch_bounds__(TPB)
dualswitch_kernel(const float4* __restrict__ in, float4* __restrict__ out) {
    int base = blockIdx.x * (TPB * UNROLL) + threadIdx.x;

    float4 v[UNROLL];
    #pragma unroll
    for (int u = 0; u < UNROLL; u++)
        v[u] = __ldcs(in + base + u * TPB);          // linear: [R + imm]

    #pragma unroll
    for (int u = 0; u < UNROLL; u++)
        __stcs(out + ((base + u * TPB) ^ 192),
               make_float4(v[u].w, v[u].z, v[u].y, v[u].x));
}

extern "C" void kernel_launch(void* const* d_in, const int* in_sizes, int n_in,
                              void* d_out, int out_size) {
    const float4* in  = (const float4*)d_in[0];
    float4*       out = (float4*)d_out;
    int total4 = out_size / 4;                     // 25,165,824
    int blocks = total4 / (TPB * UNROLL);          // exact: 12,288
    dualswitch_kernel<<<blocks, TPB>>>(in, out);
}